// round 1
// baseline (speedup 1.0000x reference)
#include <cuda_runtime.h>
#include <cuda_bf16.h>

// Problem constants (fixed by the reference setup_inputs)
#define BB 64
#define SS 512
#define HH 768
#define WW 256      // MAX_WORD_LEN
#define WE 300
#define OUTW (HH + WE)   // 1068

// One CTA per (batch, word). token_ids sorted per batch => contiguous segment;
// binary search the bounds, mean-reduce the segment rows (float4), write the
// transformer half, then copy the gathered w2v row into the concat tail.
__global__ __launch_bounds__(128)
void embeddings_fused_kernel(const float* __restrict__ hidden,
                             const float* __restrict__ w2v,
                             const int*   __restrict__ token_ids,
                             const int*   __restrict__ word_ids,
                             float*       __restrict__ out)
{
    const int bw = blockIdx.x;         // 0 .. B*W-1
    const int b  = bw >> 8;            // / WW
    const int w  = bw & (WW - 1);

    __shared__ int s_lo, s_hi;
    if (threadIdx.x == 0) {
        const int* t = token_ids + b * SS;
        // lower_bound(w)
        int lo = 0, hi = SS;
        while (lo < hi) { int m = (lo + hi) >> 1; if (t[m] < w) lo = m + 1; else hi = m; }
        s_lo = lo;
        // lower_bound(w+1), starting from lo
        int lo2 = lo, hi2 = SS;
        while (lo2 < hi2) { int m = (lo2 + hi2) >> 1; if (t[m] < w + 1) lo2 = m + 1; else hi2 = m; }
        s_hi = lo2;
    }
    __syncthreads();

    const int lo = s_lo, hi = s_hi;
    const int cnt = hi - lo;
    const float inv = (cnt > 0) ? (1.0f / (float)cnt) : 0.0f;

    float4* orow = reinterpret_cast<float4*>(out + (size_t)bw * OUTW);

    // --- transformer_hidden: mean over segment rows, H/4 = 192 float4 ---
    const float4* hbase = reinterpret_cast<const float4*>(hidden + (size_t)b * SS * HH);
    const int HV = HH / 4;  // 192
    #pragma unroll 1
    for (int i = threadIdx.x; i < HV; i += blockDim.x) {
        float4 acc = make_float4(0.f, 0.f, 0.f, 0.f);
        #pragma unroll 1
        for (int s = lo; s < hi; ++s) {
            float4 v = __ldg(&hbase[(size_t)s * HV + i]);
            acc.x += v.x; acc.y += v.y; acc.z += v.z; acc.w += v.w;
        }
        acc.x *= inv; acc.y *= inv; acc.z *= inv; acc.w *= inv;
        orow[i] = acc;
    }

    // --- word_hidden: gather w2v_table[word_ids[b,w]], WE/4 = 75 float4 ---
    const int wid = __ldg(&word_ids[b * WW + w]);
    const float4* wrow = reinterpret_cast<const float4*>(w2v + (size_t)wid * WE);
    const int WV = WE / 4;  // 75
    for (int i = threadIdx.x; i < WV; i += blockDim.x) {
        orow[HV + i] = __ldg(&wrow[i]);
    }
}

extern "C" void kernel_launch(void* const* d_in, const int* in_sizes, int n_in,
                              void* d_out, int out_size)
{
    // Identify inputs by element count (robust to ordering):
    //   hidden    : 64*512*768  = 25,165,824 (float32)
    //   w2v_table : 50000*300   = 15,000,000 (float32)
    //   token_ids : 64*512      = 32,768     (int32)
    //   word_ids  : 64*256      = 16,384     (int32)
    const float* hidden = nullptr;
    const float* w2v    = nullptr;
    const int*   tok    = nullptr;
    const int*   wids   = nullptr;
    for (int i = 0; i < n_in; ++i) {
        switch (in_sizes[i]) {
            case 25165824: hidden = (const float*)d_in[i]; break;
            case 15000000: w2v    = (const float*)d_in[i]; break;
            case 32768:    tok    = (const int*)d_in[i];   break;
            case 16384:    wids   = (const int*)d_in[i];   break;
            default: break;
        }
    }
    float* out = (float*)d_out;

    dim3 grid(BB * WW);   // 16384 CTAs
    dim3 block(128);
    embeddings_fused_kernel<<<grid, block>>>(hidden, w2v, tok, wids, out);
}

// round 5
// speedup vs baseline: 1.5788x; 1.5788x over previous
#include <cuda_runtime.h>
#include <cuda_bf16.h>

// Problem constants (fixed by the reference setup_inputs)
#define BB 64
#define SS 512
#define HH 768
#define WW 256      // MAX_WORD_LEN
#define WE 300
#define OUTW (HH + WE)   // 1068
#define HV  (HH/4)       // 192 float4
#define WV  (WE/4)       // 75 float4

// One CTA per (batch, word). token_ids sorted per batch => contiguous segment.
// All threads load token_ids into smem (coalesced), then every thread redundantly
// binary-searches smem (broadcast LDS -> no conflicts, no barrier after, no
// single-thread global-memory pointer chase). Then mean-reduce the segment with
// two independent accumulator chains per thread and write the concat row.
__global__ __launch_bounds__(128)
void embeddings_fused_kernel(const float* __restrict__ hidden,
                             const float* __restrict__ w2v,
                             const int*   __restrict__ token_ids,
                             const int*   __restrict__ word_ids,
                             float*       __restrict__ out)
{
    const int bw = blockIdx.x;         // 0 .. B*W-1
    const int b  = bw >> 8;            // / WW
    const int w  = bw & (WW - 1);
    const int tid = threadIdx.x;

    __shared__ int st[SS];
    {
        const int* tb = token_ids + b * SS;
        st[tid      ] = tb[tid      ];
        st[tid + 128] = tb[tid + 128];
        st[tid + 256] = tb[tid + 256];
        st[tid + 384] = tb[tid + 384];
    }
    __syncthreads();

    // lower_bound(w) and lower_bound(w+1) — every thread does the same search;
    // all LDS are broadcast (same address across the warp).
    int lo = 0, hi = SS;
    while (lo < hi) {
        int m = (lo + hi) >> 1;
        if (st[m] < w) lo = m + 1; else hi = m;
    }
    int lo2 = lo, hi2 = SS;
    while (lo2 < hi2) {
        int m = (lo2 + hi2) >> 1;
        if (st[m] <= w) lo2 = m + 1; else hi2 = m;
    }
    const int cnt = lo2 - lo;
    const float inv = (cnt > 0) ? (1.0f / (float)cnt) : 0.0f;

    float4* orow = reinterpret_cast<float4*>(out + (size_t)bw * OUTW);

    // --- transformer_hidden: mean over segment rows; 192 float4 across 128 thr:
    //     thread owns i0=tid and (for tid<64) i1=tid+128 -> 2 indep load chains.
    const float4* hb = reinterpret_cast<const float4*>(hidden + (size_t)b * SS * HH)
                       + (size_t)lo * HV;
    const bool has2 = (tid < (HV - 128));  // tid < 64
    float4 a0 = make_float4(0.f, 0.f, 0.f, 0.f);
    float4 a1 = make_float4(0.f, 0.f, 0.f, 0.f);
    #pragma unroll 1
    for (int s = 0; s < cnt; ++s) {
        const float4* r = hb + (size_t)s * HV;
        float4 v0 = __ldcs(&r[tid]);
        a0.x += v0.x; a0.y += v0.y; a0.z += v0.z; a0.w += v0.w;
        if (has2) {
            float4 v1 = __ldcs(&r[tid + 128]);
            a1.x += v1.x; a1.y += v1.y; a1.z += v1.z; a1.w += v1.w;
        }
    }
    a0.x *= inv; a0.y *= inv; a0.z *= inv; a0.w *= inv;
    __stcs(&orow[tid], a0);
    if (has2) {
        a1.x *= inv; a1.y *= inv; a1.z *= inv; a1.w *= inv;
        __stcs(&orow[tid + 128], a1);
    }

    // --- word_hidden: gather w2v_table[word_ids[b,w]], 75 float4 (tid < 75) ---
    const int wid = __ldg(&word_ids[bw]);
    const float4* wrow = reinterpret_cast<const float4*>(w2v + (size_t)wid * WE);
    if (tid < WV) {
        __stcs(&orow[HV + tid], __ldg(&wrow[tid]));
    }
}

extern "C" void kernel_launch(void* const* d_in, const int* in_sizes, int n_in,
                              void* d_out, int out_size)
{
    // Identify inputs by element count (robust to ordering):
    //   hidden    : 64*512*768  = 25,165,824 (float32)
    //   w2v_table : 50000*300   = 15,000,000 (float32)
    //   token_ids : 64*512      = 32,768     (int32)
    //   word_ids  : 64*256      = 16,384     (int32)
    const float* hidden = nullptr;
    const float* w2v    = nullptr;
    const int*   tok    = nullptr;
    const int*   wids   = nullptr;
    for (int i = 0; i < n_in; ++i) {
        switch (in_sizes[i]) {
            case 25165824: hidden = (const float*)d_in[i]; break;
            case 15000000: w2v    = (const float*)d_in[i]; break;
            case 32768:    tok    = (const int*)d_in[i];   break;
            case 16384:    wids   = (const int*)d_in[i];   break;
            default: break;
        }
    }
    float* out = (float*)d_out;

    dim3 grid(BB * WW);   // 16384 CTAs
    dim3 block(128);
    embeddings_fused_kernel<<<grid, block>>>(hidden, w2v, tok, wids, out);
}